// round 1
// baseline (speedup 1.0000x reference)
#include <cuda_runtime.h>

#define NNODES 20000
#define NEDGES 160000
#define BBATCH 64
#define FTEXT  300
#define FHID   1024
#define FOUT   1664
#define NEG_SLOPE 0.2f

// ---------------- scratch (static device globals; no allocation) ----------------
__device__ float g_deg[NNODES];
__device__ float g_dinv[NNODES];
__device__ int   g_cnt[NNODES];
__device__ int   g_rowptr[NNODES + 1];
__device__ int   g_cursor[NNODES];
__device__ int   g_colsrc[NEDGES];
__device__ float g_colw[NEDGES];
__device__ float g_Y[(size_t)NNODES * FTEXT];    // A @ X           [20000,300]
__device__ float g_X1[(size_t)NNODES * FHID];    // leaky(Y@W1+b1)  [20000,1024]
__device__ float g_T1[BBATCH * FHID];            // img @ W2^T      [64,1024]
__device__ float g_T2[(size_t)NNODES * BBATCH];  // X1 @ T1^T       [20000,64]
__device__ float g_outT[(size_t)NNODES * BBATCH];// out^T           [20000,64]
__device__ float g_imgb2[BBATCH];                // img @ b2        [64]

// ---------------- small kernels ----------------
__global__ void k_zero() {
    int i = blockIdx.x * blockDim.x + threadIdx.x;
    if (i < NNODES) { g_deg[i] = 0.f; g_cnt[i] = 0; g_cursor[i] = 0; }
}

__global__ void k_deg(const int* __restrict__ dst, const float* __restrict__ w) {
    int e = blockIdx.x * blockDim.x + threadIdx.x;
    if (e < NEDGES) {
        int d = dst[e];
        atomicAdd(&g_deg[d], w[e]);
        atomicAdd(&g_cnt[d], 1);
    }
}

__global__ void k_dinv() {
    int i = blockIdx.x * blockDim.x + threadIdx.x;
    if (i < NNODES) {
        float d = g_deg[i];
        g_dinv[i] = (d > 0.f) ? rsqrtf(d) : 0.f;
    }
}

// exclusive prefix sum of g_cnt -> g_rowptr (single block, 1024 threads, 20 elems each)
__global__ void k_scan() {
    __shared__ int s[1024];
    const int CH = 20;
    int t = threadIdx.x;
    int base = t * CH;
    int loc[CH];
    int sum = 0;
    #pragma unroll
    for (int i = 0; i < CH; i++) {
        int v = (base + i < NNODES) ? g_cnt[base + i] : 0;
        loc[i] = sum;
        sum += v;
    }
    s[t] = sum;
    __syncthreads();
    // inclusive scan (Hillis-Steele)
    for (int off = 1; off < 1024; off <<= 1) {
        int v = (t >= off) ? s[t - off] : 0;
        __syncthreads();
        s[t] += v;
        __syncthreads();
    }
    int pre = (t == 0) ? 0 : s[t - 1];
    #pragma unroll
    for (int i = 0; i < CH; i++) {
        if (base + i < NNODES) g_rowptr[base + i] = pre + loc[i];
    }
    if (t == 1023) g_rowptr[NNODES] = s[1023];
}

__global__ void k_fill(const int* __restrict__ src, const int* __restrict__ dst,
                       const float* __restrict__ w) {
    int e = blockIdx.x * blockDim.x + threadIdx.x;
    if (e < NEDGES) {
        int s = src[e], d = dst[e];
        float nm = g_dinv[s] * w[e] * g_dinv[d];
        int pos = g_rowptr[d] + atomicAdd(&g_cursor[d], 1);
        g_colsrc[pos] = s;
        g_colw[pos]   = nm;
    }
}

// Y[n,:] = sum over incoming edges of norm * X[src,:], width 300
__global__ void k_aggY(const float* __restrict__ X) {
    __shared__ int   ss[128];
    __shared__ float sw[128];
    int n = blockIdx.x;
    int tid = threadIdx.x;
    int st = g_rowptr[n], en = g_rowptr[n + 1];
    float acc0 = 0.f, acc1 = 0.f, acc2 = 0.f;
    for (int e0 = st; e0 < en; e0 += 128) {
        int ne = min(128, en - e0);
        if (tid < ne) { ss[tid] = g_colsrc[e0 + tid]; sw[tid] = g_colw[e0 + tid]; }
        __syncthreads();
        for (int j = 0; j < ne; j++) {
            const float* xr = X + (size_t)ss[j] * FTEXT;
            float wv = sw[j];
            int c0 = tid;
            acc0 += wv * xr[c0];
            int c1 = tid + 128;
            acc1 += wv * xr[c1];
            int c2 = tid + 256;
            if (c2 < FTEXT) acc2 += wv * xr[c2];
        }
        __syncthreads();
    }
    float* yr = g_Y + (size_t)n * FTEXT;
    yr[tid] = acc0;
    yr[tid + 128] = acc1;
    if (tid + 256 < FTEXT) yr[tid + 256] = acc2;
}

// ---------------- GEMM1: X1 = leaky(Y @ W1 + b1), NN layout ----------------
// Y [20000,300] rm, W1 [300,1024] rm, out [20000,1024]
// BM=64, BN=64, BK=20 (300 = 15*20), 256 threads, 4x4 microtile
__global__ void k_gemm1(const float* __restrict__ W1, const float* __restrict__ b1) {
    const int BM = 64, BN = 64, BK = 20;
    __shared__ float As[BK][BM + 1];
    __shared__ float Bs[BK][BN + 1];
    int tid = threadIdx.x;
    int tx = tid & 15, ty = tid >> 4;
    int row0 = blockIdx.y * BM;
    int col0 = blockIdx.x * BN;

    float acc[4][4] = {};

    for (int t0 = 0; t0 < FTEXT; t0 += BK) {
        // load A tile (transposed into As[k][r])
        #pragma unroll
        for (int l = 0; l < 5; l++) {
            int idx = tid + l * 256;          // 0..1279
            int k = idx % BK, r = idx / BK;
            int row = row0 + r;
            As[k][r] = (row < NNODES) ? g_Y[(size_t)row * FTEXT + t0 + k] : 0.f;
        }
        // load B tile Bs[k][c]
        #pragma unroll
        for (int l = 0; l < 5; l++) {
            int idx = tid + l * 256;
            int c = idx & 63, kk = idx >> 6;
            Bs[kk][c] = W1[(size_t)(t0 + kk) * FHID + col0 + c];
        }
        __syncthreads();
        #pragma unroll
        for (int k = 0; k < BK; k++) {
            float a[4], b[4];
            #pragma unroll
            for (int i = 0; i < 4; i++) a[i] = As[k][ty * 4 + i];
            #pragma unroll
            for (int j = 0; j < 4; j++) b[j] = Bs[k][tx * 4 + j];
            #pragma unroll
            for (int i = 0; i < 4; i++)
                #pragma unroll
                for (int j = 0; j < 4; j++)
                    acc[i][j] += a[i] * b[j];
        }
        __syncthreads();
    }
    #pragma unroll
    for (int i = 0; i < 4; i++) {
        int row = row0 + ty * 4 + i;
        if (row >= NNODES) continue;
        #pragma unroll
        for (int j = 0; j < 4; j++) {
            int col = col0 + tx * 4 + j;
            float v = acc[i][j] + b1[col];
            v = (v >= 0.f) ? v : NEG_SLOPE * v;
            g_X1[(size_t)row * FHID + col] = v;
        }
    }
}

// ---------------- generic NT GEMM: C[m,n] = sum_k A[m,k]*B[n,k] ----------------
// A [M,K] rm lda, B [N,K] rm ldb, C [M,N] rm ldc. BM=BN=64, BK=16.
__global__ void k_gemm_nt(const float* __restrict__ A, int lda,
                          const float* __restrict__ B, int ldb,
                          float* __restrict__ C, int ldc,
                          int M, int N, int K) {
    const int BM = 64, BN = 64, BK = 16;
    __shared__ float As[BK][BM + 1];
    __shared__ float Bs[BK][BN + 1];
    int tid = threadIdx.x;
    int tx = tid & 15, ty = tid >> 4;
    int row0 = blockIdx.y * BM;
    int col0 = blockIdx.x * BN;

    float acc[4][4] = {};

    for (int t0 = 0; t0 < K; t0 += BK) {
        #pragma unroll
        for (int l = 0; l < 4; l++) {
            int idx = tid + l * 256;          // 0..1023
            int k = idx & 15, r = idx >> 4;
            int row = row0 + r;
            As[k][r] = (row < M && t0 + k < K) ? A[(size_t)row * lda + t0 + k] : 0.f;
        }
        #pragma unroll
        for (int l = 0; l < 4; l++) {
            int idx = tid + l * 256;
            int k = idx & 15, c = idx >> 4;
            int col = col0 + c;
            Bs[k][c] = (col < N && t0 + k < K) ? B[(size_t)col * ldb + t0 + k] : 0.f;
        }
        __syncthreads();
        #pragma unroll
        for (int k = 0; k < BK; k++) {
            float a[4], b[4];
            #pragma unroll
            for (int i = 0; i < 4; i++) a[i] = As[k][ty * 4 + i];
            #pragma unroll
            for (int j = 0; j < 4; j++) b[j] = Bs[k][tx * 4 + j];
            #pragma unroll
            for (int i = 0; i < 4; i++)
                #pragma unroll
                for (int j = 0; j < 4; j++)
                    acc[i][j] += a[i] * b[j];
        }
        __syncthreads();
    }
    #pragma unroll
    for (int i = 0; i < 4; i++) {
        int row = row0 + ty * 4 + i;
        if (row >= M) continue;
        #pragma unroll
        for (int j = 0; j < 4; j++) {
            int col = col0 + tx * 4 + j;
            if (col < N) C[(size_t)row * ldc + col] = acc[i][j];
        }
    }
}

// imgb2[b] = dot(img[b,:], b2)
__global__ void k_imgb2(const float* __restrict__ img, const float* __restrict__ b2) {
    __shared__ float s[256];
    int b = blockIdx.x;
    int tid = threadIdx.x;
    float acc = 0.f;
    for (int i = tid; i < FOUT; i += 256)
        acc += img[(size_t)b * FOUT + i] * b2[i];
    s[tid] = acc;
    __syncthreads();
    for (int off = 128; off > 0; off >>= 1) {
        if (tid < off) s[tid] += s[tid + off];
        __syncthreads();
    }
    if (tid == 0) g_imgb2[b] = s[0];
}

// outT[n,b] = imgb2[b] + sum over incoming edges of norm * T2[src,b]
__global__ void k_aggOut() {
    int n = blockIdx.x * 4 + (threadIdx.x >> 6);
    int b = threadIdx.x & 63;
    if (n >= NNODES) return;
    float acc = g_imgb2[b];
    int st = g_rowptr[n], en = g_rowptr[n + 1];
    for (int e = st; e < en; e++)
        acc += g_colw[e] * g_T2[(size_t)g_colsrc[e] * BBATCH + b];
    g_outT[(size_t)n * BBATCH + b] = acc;
}

// out[b, n] = outT[n, b]  (tiled transpose)
__global__ void k_transpose(float* __restrict__ out) {
    __shared__ float s[32][33];
    int n0 = blockIdx.x * 32;
    int b0 = blockIdx.y * 32;
    // read coalesced over b
    #pragma unroll
    for (int i = 0; i < 32; i += 8) {
        int n = n0 + threadIdx.y + i;
        int b = b0 + threadIdx.x;
        if (n < NNODES) s[threadIdx.y + i][threadIdx.x] = g_outT[(size_t)n * BBATCH + b];
    }
    __syncthreads();
    // write coalesced over n
    #pragma unroll
    for (int i = 0; i < 32; i += 8) {
        int n = n0 + threadIdx.x;
        int b = b0 + threadIdx.y + i;
        if (n < NNODES) out[(size_t)b * NNODES + n] = s[threadIdx.x][threadIdx.y + i];
    }
}

// ---------------- launch ----------------
extern "C" void kernel_launch(void* const* d_in, const int* in_sizes, int n_in,
                              void* d_out, int out_size) {
    const float* img  = (const float*)d_in[0];   // [64,1664]
    const float* nf   = (const float*)d_in[1];   // [20000,300]
    const int*   esrc = (const int*)d_in[2];     // [E]
    const int*   edst = (const int*)d_in[3];     // [E]
    const float* ew   = (const float*)d_in[4];   // [E]
    const float* W1   = (const float*)d_in[5];   // [300,1024]
    const float* b1   = (const float*)d_in[6];   // [1024]
    const float* W2   = (const float*)d_in[7];   // [1024,1664]
    const float* b2   = (const float*)d_in[8];   // [1664]
    float* out = (float*)d_out;                  // [64,20000]

    // pointers to device globals (valid to use directly from kernels)
    float* dT1; cudaGetSymbolAddress((void**)&dT1, g_T1);
    float* dX1; cudaGetSymbolAddress((void**)&dX1, g_X1);
    float* dT2; cudaGetSymbolAddress((void**)&dT2, g_T2);

    k_zero<<<(NNODES + 255) / 256, 256>>>();
    k_deg<<<(NEDGES + 255) / 256, 256>>>(edst, ew);
    k_dinv<<<(NNODES + 255) / 256, 256>>>();
    k_scan<<<1, 1024>>>();
    k_fill<<<(NEDGES + 255) / 256, 256>>>(esrc, edst, ew);

    // layer 1: Y = A @ X, then X1 = leaky(Y @ W1 + b1)
    k_aggY<<<NNODES, 128>>>(nf);
    {
        dim3 grid(FHID / 64, (NNODES + 63) / 64);
        k_gemm1<<<grid, 256>>>(W1, b1);
    }

    // T1 = img @ W2^T  [64,1024]
    {
        dim3 grid((FHID + 63) / 64, (BBATCH + 63) / 64);
        k_gemm_nt<<<grid, 256>>>(img, FOUT, W2, FOUT, dT1, FHID, BBATCH, FHID, FOUT);
    }
    k_imgb2<<<BBATCH, 256>>>(img, b2);

    // T2 = X1 @ T1^T  [20000,64]
    {
        dim3 grid((BBATCH + 63) / 64, (NNODES + 63) / 64);
        k_gemm_nt<<<grid, 256>>>(dX1, FHID, dT1, FHID, dT2, BBATCH, NNODES, BBATCH, FHID);
    }

    // out^T[n,b] = imgb2[b] + sum_e norm * T2[src,b]; then transpose
    k_aggOut<<<(NNODES + 3) / 4, 256>>>();
    {
        dim3 grid((NNODES + 31) / 32, BBATCH / 32);
        k_transpose<<<grid, dim3(32, 8)>>>(out);
    }
}

// round 3
// speedup vs baseline: 2.5939x; 2.5939x over previous
#include <cuda_runtime.h>
#include <cuda_bf16.h>
#include <cstdint>

#define NNODES 20000
#define NEDGES 160000
#define BBATCH 64
#define FTEXT  300
#define FHID   1024
#define FOUT   1664
#define NEG_SLOPE 0.2f

// ---------------- scratch ----------------
__device__ float g_deg[NNODES];
__device__ float g_dinv[NNODES];
__device__ int   g_cnt[NNODES];
__device__ int   g_rowptr[NNODES + 1];
__device__ int   g_cursor[NNODES];
__device__ int   g_colsrc[NEDGES];
__device__ float g_colw[NEDGES];
__device__ float g_Y[(size_t)NNODES * FTEXT];     // A @ X            [20000,300]
__device__ float g_X1[(size_t)NNODES * FHID];     // leaky(Y@W1+b1)   [20000,1024]
__device__ float g_W1t[(size_t)FHID * FTEXT];     // W1^T             [1024,300]
__device__ float g_T1[BBATCH * FHID];             // img @ W2^T       [64,1024]
__device__ float g_T2[(size_t)NNODES * BBATCH];   // X1 @ T1^T        [20000,64]
__device__ float g_outT[(size_t)NNODES * BBATCH];
__device__ float g_imgb2[BBATCH];

// ---------------- PTX helpers (non-'a' baseline features only) ----------------
__device__ __forceinline__ uint32_t smem_to_u32(const void* p) {
    uint32_t a;
    asm("{ .reg .u64 t; cvta.to.shared.u64 t, %1; cvt.u32.u64 %0, t; }" : "=r"(a) : "l"(p));
    return a;
}
__device__ __forceinline__ void ldsm_x4(uint32_t* r, uint32_t addr) {
    asm volatile("ldmatrix.sync.aligned.m8n8.x4.shared.b16 {%0,%1,%2,%3}, [%4];"
        : "=r"(r[0]), "=r"(r[1]), "=r"(r[2]), "=r"(r[3]) : "r"(addr));
}
__device__ __forceinline__ void mma_bf16(float* c, const uint32_t* a, const uint32_t* b) {
    asm volatile(
        "mma.sync.aligned.m16n8k16.row.col.f32.bf16.bf16.f32 "
        "{%0,%1,%2,%3}, {%4,%5,%6,%7}, {%8,%9}, {%0,%1,%2,%3};"
        : "+f"(c[0]), "+f"(c[1]), "+f"(c[2]), "+f"(c[3])
        : "r"(a[0]), "r"(a[1]), "r"(a[2]), "r"(a[3]), "r"(b[0]), "r"(b[1]));
}
__device__ __forceinline__ void f4_hilo(float4 v, uint2& h, uint2& l) {
    __nv_bfloat16 hx = __float2bfloat16_rn(v.x);
    __nv_bfloat16 hy = __float2bfloat16_rn(v.y);
    __nv_bfloat16 hz = __float2bfloat16_rn(v.z);
    __nv_bfloat16 hw = __float2bfloat16_rn(v.w);
    __nv_bfloat16 lx = __float2bfloat16_rn(v.x - __bfloat162float(hx));
    __nv_bfloat16 ly = __float2bfloat16_rn(v.y - __bfloat162float(hy));
    __nv_bfloat16 lz = __float2bfloat16_rn(v.z - __bfloat162float(hz));
    __nv_bfloat16 lw = __float2bfloat16_rn(v.w - __bfloat162float(hw));
    __nv_bfloat162 h01(hx, hy), h23(hz, hw), l01(lx, ly), l23(lz, lw);
    h.x = *(uint32_t*)&h01; h.y = *(uint32_t*)&h23;
    l.x = *(uint32_t*)&l01; l.y = *(uint32_t*)&l23;
}

// ---------------- CSR build ----------------
__global__ void k_zero() {
    int i = blockIdx.x * blockDim.x + threadIdx.x;
    if (i < NNODES) { g_deg[i] = 0.f; g_cnt[i] = 0; g_cursor[i] = 0; }
}
__global__ void k_deg(const int* __restrict__ dst, const float* __restrict__ w) {
    int e = blockIdx.x * blockDim.x + threadIdx.x;
    if (e < NEDGES) {
        int d = dst[e];
        atomicAdd(&g_deg[d], w[e]);
        atomicAdd(&g_cnt[d], 1);
    }
}
__global__ void k_dinv() {
    int i = blockIdx.x * blockDim.x + threadIdx.x;
    if (i < NNODES) {
        float d = g_deg[i];
        g_dinv[i] = (d > 0.f) ? rsqrtf(d) : 0.f;
    }
}
__global__ void k_scan() {
    __shared__ int s[1024];
    const int CH = 20;
    int t = threadIdx.x;
    int base = t * CH;
    int loc[CH];
    int sum = 0;
    #pragma unroll
    for (int i = 0; i < CH; i++) {
        int v = (base + i < NNODES) ? g_cnt[base + i] : 0;
        loc[i] = sum;
        sum += v;
    }
    s[t] = sum;
    __syncthreads();
    for (int off = 1; off < 1024; off <<= 1) {
        int v = (t >= off) ? s[t - off] : 0;
        __syncthreads();
        s[t] += v;
        __syncthreads();
    }
    int pre = (t == 0) ? 0 : s[t - 1];
    #pragma unroll
    for (int i = 0; i < CH; i++) {
        if (base + i < NNODES) g_rowptr[base + i] = pre + loc[i];
    }
    if (t == 1023) g_rowptr[NNODES] = s[1023];
}
__global__ void k_fill(const int* __restrict__ src, const int* __restrict__ dst,
                       const float* __restrict__ w) {
    int e = blockIdx.x * blockDim.x + threadIdx.x;
    if (e < NEDGES) {
        int s = src[e], d = dst[e];
        float nm = g_dinv[s] * w[e] * g_dinv[d];
        int pos = g_rowptr[d] + atomicAdd(&g_cursor[d], 1);
        g_colsrc[pos] = s;
        g_colw[pos]   = nm;
    }
}

// Y[n,:] = sum incoming norm * X[src,:], width 300
__global__ void k_aggY(const float* __restrict__ X) {
    __shared__ int   ss[128];
    __shared__ float sw[128];
    int n = blockIdx.x;
    int tid = threadIdx.x;
    int st = g_rowptr[n], en = g_rowptr[n + 1];
    float acc0 = 0.f, acc1 = 0.f, acc2 = 0.f;
    for (int e0 = st; e0 < en; e0 += 128) {
        int ne = min(128, en - e0);
        if (tid < ne) { ss[tid] = g_colsrc[e0 + tid]; sw[tid] = g_colw[e0 + tid]; }
        __syncthreads();
        for (int j = 0; j < ne; j++) {
            const float* xr = X + (size_t)ss[j] * FTEXT;
            float wv = sw[j];
            acc0 += wv * xr[tid];
            acc1 += wv * xr[tid + 128];
            if (tid + 256 < FTEXT) acc2 += wv * xr[tid + 256];
        }
        __syncthreads();
    }
    float* yr = g_Y + (size_t)n * FTEXT;
    yr[tid] = acc0;
    yr[tid + 128] = acc1;
    if (tid + 256 < FTEXT) yr[tid + 256] = acc2;
}

// W1t[n,k] = W1[k,n]
__global__ void k_transW1(const float* __restrict__ W1) {
    __shared__ float s[32][33];
    int n0 = blockIdx.x * 32, k0 = blockIdx.y * 32;
    int tx = threadIdx.x, ty = threadIdx.y;  // 32x8
    #pragma unroll
    for (int i = 0; i < 32; i += 8) {
        int k = k0 + ty + i, n = n0 + tx;
        if (k < FTEXT) s[ty + i][tx] = W1[(size_t)k * FHID + n];
    }
    __syncthreads();
    #pragma unroll
    for (int i = 0; i < 32; i += 8) {
        int n = n0 + ty + i, k = k0 + tx;
        if (k < FTEXT) g_W1t[(size_t)n * FTEXT + k] = s[tx][ty + i];
    }
}

// ---------------- bf16x3 mma.sync GEMM ----------------
// C[M,N] = A[M,K] @ B[N,K]^T ; A,B row-major K-contiguous, K % 4 == 0.
// CTA tile 128x64, BK=32 floats, double-buffered smem, 256 threads (8 warps 4x2).
// Each fp32 operand split hi/lo bf16; MMAs: hh + hl + lh -> ~1e-5 relative error.
template<bool BIAS, bool LEAKY>
__global__ void __launch_bounds__(256, 2) mma_gemm(
    const float* __restrict__ A, int lda,
    const float* __restrict__ B, int ldb,
    float* __restrict__ C, int ldc,
    const float* __restrict__ bias,
    int M, int N, int K)
{
    extern __shared__ char smem[];
    const int STRIDE  = 40;                 // bf16 elems per smem row (80 B, conflict-free ldmatrix)
    const int A_BYTES = 128 * STRIDE * 2;   // 10240
    const int B_BYTES = 64  * STRIDE * 2;   // 5120
    const int STAGE   = 2 * A_BYTES + 2 * B_BYTES;  // 30720

    int tid  = threadIdx.x;
    int wid  = tid >> 5, lane = tid & 31;
    int wm   = wid & 3;                     // m-warp 0..3 (32 rows each)
    int wn   = wid >> 2;                    // n-warp 0..1 (32 cols each)
    int row0 = blockIdx.y * 128;
    int col0 = blockIdx.x * 64;

    uint32_t smem_u = smem_to_u32(smem);

    float acc[2][4][4];
    #pragma unroll
    for (int mt = 0; mt < 2; mt++)
        #pragma unroll
        for (int nt = 0; nt < 4; nt++)
            #pragma unroll
            for (int q = 0; q < 4; q++) acc[mt][nt][q] = 0.f;

    float4 aR[4], bR[2];

    const int nT = (K + 31) >> 5;

    // ---- helpers as lambdas ----
    auto LDG = [&](int t) {
        int kb = t * 32;
        #pragma unroll
        for (int i = 0; i < 4; i++) {
            int idx = tid + i * 256;        // 0..1023 float4s
            int r = idx >> 3, kk = (idx & 7) * 4;
            int row = row0 + r, kg = kb + kk;
            float4 v = make_float4(0.f, 0.f, 0.f, 0.f);
            if (row < M && kg < K) v = *(const float4*)(A + (size_t)row * lda + kg);
            aR[i] = v;
        }
        #pragma unroll
        for (int i = 0; i < 2; i++) {
            int idx = tid + i * 256;        // 0..511
            int c = idx >> 3, kk = (idx & 7) * 4;
            int col = col0 + c, kg = kb + kk;
            float4 v = make_float4(0.f, 0.f, 0.f, 0.f);
            if (col < N && kg < K) v = *(const float4*)(B + (size_t)col * ldb + kg);
            bR[i] = v;
        }
    };
    auto STS = [&](int s) {
        char* base = smem + s * STAGE;
        #pragma unroll
        for (int i = 0; i < 4; i++) {
            int idx = tid + i * 256;
            int r = idx >> 3, kk = (idx & 7) * 4;
            uint2 h, l;
            f4_hilo(aR[i], h, l);
            *(uint2*)(base + r * 80 + kk * 2) = h;
            *(uint2*)(base + A_BYTES + r * 80 + kk * 2) = l;
        }
        #pragma unroll
        for (int i = 0; i < 2; i++) {
            int idx = tid + i * 256;
            int c = idx >> 3, kk = (idx & 7) * 4;
            uint2 h, l;
            f4_hilo(bR[i], h, l);
            *(uint2*)(base + 2 * A_BYTES + c * 80 + kk * 2) = h;
            *(uint2*)(base + 2 * A_BYTES + B_BYTES + c * 80 + kk * 2) = l;
        }
    };
    auto COMPUTE = [&](int s) {
        uint32_t sb = smem_u + s * STAGE;
        // A ldmatrix addr: row = wm*32 + (lane&15) (+16 per mtile), k8 = lane>>4
        uint32_t aH = sb + (uint32_t)((wm * 32 + (lane & 15)) * 80 + (lane >> 4) * 16);
        uint32_t aL = aH + A_BYTES;
        // B ldmatrix addr: n = wn*32 + ((lane>>4)&1)*8 + (lane&7) (+16 per pair-group), k8 = (lane>>3)&1
        uint32_t bH = sb + 2 * A_BYTES +
            (uint32_t)((wn * 32 + ((lane >> 4) & 1) * 8 + (lane & 7)) * 80 + ((lane >> 3) & 1) * 16);
        uint32_t bL = bH + B_BYTES;
        #pragma unroll
        for (int ks = 0; ks < 2; ks++) {
            uint32_t ah[2][4], al[2][4], bh[2][4], bl[2][4];
            #pragma unroll
            for (int mt = 0; mt < 2; mt++) {
                ldsm_x4(ah[mt], aH + mt * 16 * 80 + ks * 32);
                ldsm_x4(al[mt], aL + mt * 16 * 80 + ks * 32);
            }
            #pragma unroll
            for (int g = 0; g < 2; g++) {
                ldsm_x4(bh[g], bH + g * 16 * 80 + ks * 32);
                ldsm_x4(bl[g], bL + g * 16 * 80 + ks * 32);
            }
            #pragma unroll
            for (int mt = 0; mt < 2; mt++)
                #pragma unroll
                for (int nt = 0; nt < 4; nt++) {
                    const uint32_t* ph = &bh[nt >> 1][(nt & 1) * 2];
                    const uint32_t* pl = &bl[nt >> 1][(nt & 1) * 2];
                    mma_bf16(acc[mt][nt], ah[mt], ph);
                    mma_bf16(acc[mt][nt], ah[mt], pl);
                    mma_bf16(acc[mt][nt], al[mt], ph);
                }
        }
    };

    // ---- pipeline ----
    LDG(0);
    STS(0);
    if (nT > 1) LDG(1);
    __syncthreads();
    for (int t = 0; t < nT; t++) {
        COMPUTE(t & 1);
        if (t + 1 < nT) STS((t + 1) & 1);
        __syncthreads();
        if (t + 2 < nT) LDG(t + 2);
    }

    // ---- epilogue ----
    int rw = row0 + wm * 32;
    int cw = col0 + wn * 32;
    #pragma unroll
    for (int mt = 0; mt < 2; mt++) {
        #pragma unroll
        for (int half = 0; half < 2; half++) {
            int row = rw + mt * 16 + (lane >> 2) + half * 8;
            if (row >= M) continue;
            #pragma unroll
            for (int nt = 0; nt < 4; nt++) {
                int col = cw + nt * 8 + (lane & 3) * 2;
                if (col >= N) continue;
                float v0 = acc[mt][nt][half * 2 + 0];
                float v1 = acc[mt][nt][half * 2 + 1];
                if (BIAS) { v0 += bias[col]; v1 += bias[col + 1]; }
                if (LEAKY) {
                    v0 = (v0 >= 0.f) ? v0 : NEG_SLOPE * v0;
                    v1 = (v1 >= 0.f) ? v1 : NEG_SLOPE * v1;
                }
                float2 o; o.x = v0; o.y = v1;
                *(float2*)(C + (size_t)row * ldc + col) = o;
            }
        }
    }
}

// imgb2[b] = dot(img[b,:], b2)
__global__ void k_imgb2(const float* __restrict__ img, const float* __restrict__ b2) {
    __shared__ float s[256];
    int b = blockIdx.x;
    int tid = threadIdx.x;
    float acc = 0.f;
    for (int i = tid; i < FOUT; i += 256)
        acc += img[(size_t)b * FOUT + i] * b2[i];
    s[tid] = acc;
    __syncthreads();
    for (int off = 128; off > 0; off >>= 1) {
        if (tid < off) s[tid] += s[tid + off];
        __syncthreads();
    }
    if (tid == 0) g_imgb2[b] = s[0];
}

// outT[n,b] = imgb2[b] + sum incoming norm * T2[src,b]
__global__ void k_aggOut() {
    int n = blockIdx.x * 4 + (threadIdx.x >> 6);
    int b = threadIdx.x & 63;
    if (n >= NNODES) return;
    float acc = g_imgb2[b];
    int st = g_rowptr[n], en = g_rowptr[n + 1];
    for (int e = st; e < en; e++)
        acc += g_colw[e] * g_T2[(size_t)g_colsrc[e] * BBATCH + b];
    g_outT[(size_t)n * BBATCH + b] = acc;
}

// out[b,n] = outT[n,b]
__global__ void k_transpose(float* __restrict__ out) {
    __shared__ float s[32][33];
    int n0 = blockIdx.x * 32;
    int b0 = blockIdx.y * 32;
    #pragma unroll
    for (int i = 0; i < 32; i += 8) {
        int n = n0 + threadIdx.y + i;
        int b = b0 + threadIdx.x;
        if (n < NNODES) s[threadIdx.y + i][threadIdx.x] = g_outT[(size_t)n * BBATCH + b];
    }
    __syncthreads();
    #pragma unroll
    for (int i = 0; i < 32; i += 8) {
        int n = n0 + threadIdx.x;
        int b = b0 + threadIdx.y + i;
        if (n < NNODES) out[(size_t)b * NNODES + n] = s[threadIdx.x][threadIdx.y + i];
    }
}

// ---------------- launch ----------------
extern "C" void kernel_launch(void* const* d_in, const int* in_sizes, int n_in,
                              void* d_out, int out_size) {
    const float* img  = (const float*)d_in[0];
    const float* nf   = (const float*)d_in[1];
    const int*   esrc = (const int*)d_in[2];
    const int*   edst = (const int*)d_in[3];
    const float* ew   = (const float*)d_in[4];
    const float* W1   = (const float*)d_in[5];
    const float* b1   = (const float*)d_in[6];
    const float* W2   = (const float*)d_in[7];
    const float* b2   = (const float*)d_in[8];
    float* out = (float*)d_out;

    float* dY;   cudaGetSymbolAddress((void**)&dY,   g_Y);
    float* dX1;  cudaGetSymbolAddress((void**)&dX1,  g_X1);
    float* dW1t; cudaGetSymbolAddress((void**)&dW1t, g_W1t);
    float* dT1;  cudaGetSymbolAddress((void**)&dT1,  g_T1);
    float* dT2;  cudaGetSymbolAddress((void**)&dT2,  g_T2);

    const int SMEM = 61440;  // 2 stages x 30720
    cudaFuncSetAttribute(mma_gemm<true,  true >, cudaFuncAttributeMaxDynamicSharedMemorySize, SMEM);
    cudaFuncSetAttribute(mma_gemm<false, false>, cudaFuncAttributeMaxDynamicSharedMemorySize, SMEM);

    // CSR build
    k_zero<<<(NNODES + 255) / 256, 256>>>();
    k_deg<<<(NEDGES + 255) / 256, 256>>>(edst, ew);
    k_dinv<<<(NNODES + 255) / 256, 256>>>();
    k_scan<<<1, 1024>>>();
    k_fill<<<(NEDGES + 255) / 256, 256>>>(esrc, edst, ew);

    // W1 transpose (independent)
    {
        dim3 grid(FHID / 32, (FTEXT + 31) / 32);
        k_transW1<<<grid, dim3(32, 8)>>>(W1);
    }

    // layer 1 aggregation (width 300)
    k_aggY<<<NNODES, 128>>>(nf);

    // X1 = leaky(Y @ W1 + b1): A=g_Y [20000,300], B=g_W1t [1024,300]
    {
        dim3 grid(FHID / 64, (NNODES + 127) / 128);
        mma_gemm<true, true><<<grid, 256, SMEM>>>(
            dY, FTEXT, dW1t, FTEXT, dX1, FHID, b1, NNODES, FHID, FTEXT);
    }

    // T1 = img @ W2^T: A=img [64,1664], B=W2 [1024,1664]
    {
        dim3 grid(FHID / 64, 1);
        mma_gemm<false, false><<<grid, 256, SMEM>>>(
            img, FOUT, W2, FOUT, dT1, FHID, nullptr, BBATCH, FHID, FOUT);
    }
    k_imgb2<<<BBATCH, 256>>>(img, b2);

    // T2 = X1 @ T1^T: A=g_X1 [20000,1024], B=g_T1 [64,1024]
    {
        dim3 grid(1, (NNODES + 127) / 128);
        mma_gemm<false, false><<<grid, 256, SMEM>>>(
            dX1, FHID, dT1, FHID, dT2, BBATCH, nullptr, NNODES, BBATCH, FHID);
    }

    // output aggregation + transpose
    k_aggOut<<<(NNODES + 3) / 4, 256>>>();
    {
        dim3 grid((NNODES + 31) / 32, BBATCH / 32);
        k_transpose<<<grid, dim3(32, 8)>>>(out);
    }
}

// round 4
// speedup vs baseline: 2.7884x; 1.0750x over previous
#include <cuda_runtime.h>
#include <cuda_bf16.h>
#include <cstdint>

#define NNODES 20000
#define NEDGES 160000
#define BBATCH 64
#define FTEXT  300
#define FHID   1024
#define FOUT   1664
#define NEG_SLOPE 0.2f
#define NSPLIT 13          // T1 split-K factor (13 * 128 = 1664)

// ---------------- scratch ----------------
__device__ float g_deg[NNODES];
__device__ float g_dinv[NNODES];
__device__ int   g_cnt[NNODES];
__device__ int   g_rowptr[NNODES + 1];
__device__ int   g_cursor[NNODES];
__device__ int   g_colsrc[NEDGES];
__device__ float g_colw[NEDGES];
__device__ float g_Y[(size_t)NNODES * FTEXT];     // A @ X            [20000,300]
__device__ float g_X1[(size_t)NNODES * FHID];     // leaky(Y@W1+b1)   [20000,1024]
__device__ float g_W1t[(size_t)FHID * FTEXT];     // W1^T             [1024,300]
__device__ float g_T1p[(size_t)NSPLIT * BBATCH * FHID]; // T1 partials
__device__ float g_T1[BBATCH * FHID];             // img @ W2^T       [64,1024]
__device__ float g_T2[(size_t)NNODES * BBATCH];   // X1 @ T1^T        [20000,64]
__device__ float g_imgb2[BBATCH];

// ---------------- PTX helpers (baseline sm_80+ features only) ----------------
__device__ __forceinline__ uint32_t smem_to_u32(const void* p) {
    uint32_t a;
    asm("{ .reg .u64 t; cvta.to.shared.u64 t, %1; cvt.u32.u64 %0, t; }" : "=r"(a) : "l"(p));
    return a;
}
__device__ __forceinline__ void ldsm_x4(uint32_t* r, uint32_t addr) {
    asm volatile("ldmatrix.sync.aligned.m8n8.x4.shared.b16 {%0,%1,%2,%3}, [%4];"
        : "=r"(r[0]), "=r"(r[1]), "=r"(r[2]), "=r"(r[3]) : "r"(addr));
}
__device__ __forceinline__ void mma_bf16(float* c, const uint32_t* a, const uint32_t* b) {
    asm volatile(
        "mma.sync.aligned.m16n8k16.row.col.f32.bf16.bf16.f32 "
        "{%0,%1,%2,%3}, {%4,%5,%6,%7}, {%8,%9}, {%0,%1,%2,%3};"
        : "+f"(c[0]), "+f"(c[1]), "+f"(c[2]), "+f"(c[3])
        : "r"(a[0]), "r"(a[1]), "r"(a[2]), "r"(a[3]), "r"(b[0]), "r"(b[1]));
}
__device__ __forceinline__ void f4_hilo(float4 v, uint2& h, uint2& l) {
    __nv_bfloat16 hx = __float2bfloat16_rn(v.x);
    __nv_bfloat16 hy = __float2bfloat16_rn(v.y);
    __nv_bfloat16 hz = __float2bfloat16_rn(v.z);
    __nv_bfloat16 hw = __float2bfloat16_rn(v.w);
    __nv_bfloat16 lx = __float2bfloat16_rn(v.x - __bfloat162float(hx));
    __nv_bfloat16 ly = __float2bfloat16_rn(v.y - __bfloat162float(hy));
    __nv_bfloat16 lz = __float2bfloat16_rn(v.z - __bfloat162float(hz));
    __nv_bfloat16 lw = __float2bfloat16_rn(v.w - __bfloat162float(hw));
    __nv_bfloat162 h01(hx, hy), h23(hz, hw), l01(lx, ly), l23(lz, lw);
    h.x = *(uint32_t*)&h01; h.y = *(uint32_t*)&h23;
    l.x = *(uint32_t*)&l01; l.y = *(uint32_t*)&l23;
}

// ---------------- launch 0: zero scratch + transpose W1 ----------------
__global__ void k_init(const float* __restrict__ W1) {
    const int ZBLK = 79;                       // 79*256 >= 20000
    int tid = threadIdx.x;
    if (blockIdx.x < ZBLK) {
        int i = blockIdx.x * 256 + tid;
        if (i < NNODES) { g_deg[i] = 0.f; g_cnt[i] = 0; g_cursor[i] = 0; }
    } else {
        __shared__ float s[32][33];
        int bidx = blockIdx.x - ZBLK;          // 0..319
        int n0 = (bidx & 31) * 32;             // 32 n-tiles
        int k0 = (bidx >> 5) * 32;             // 10 k-tiles
        int tx = tid & 31, ty = tid >> 5;      // 32 x 8
        #pragma unroll
        for (int i = 0; i < 32; i += 8) {
            int k = k0 + ty + i, n = n0 + tx;
            if (k < FTEXT) s[ty + i][tx] = W1[(size_t)k * FHID + n];
        }
        __syncthreads();
        #pragma unroll
        for (int i = 0; i < 32; i += 8) {
            int n = n0 + ty + i, k = k0 + tx;
            if (k < FTEXT) g_W1t[(size_t)n * FTEXT + k] = s[tx][ty + i];
        }
    }
}

// ---------------- launch 1: degree ----------------
__global__ void k_deg(const int* __restrict__ dst, const float* __restrict__ w) {
    int e = blockIdx.x * blockDim.x + threadIdx.x;
    if (e < NEDGES) {
        int d = dst[e];
        atomicAdd(&g_deg[d], w[e]);
        atomicAdd(&g_cnt[d], 1);
    }
}

// ---------------- launch 2: warp-shuffle scan + dinv ----------------
__global__ void k_scandinv() {
    const int CH = 20;
    __shared__ int wtot[32];
    __shared__ int s_total;
    int t = threadIdx.x;
    int lane = t & 31, wid = t >> 5;
    int base = t * CH;
    int loc[CH];
    int sum = 0;
    #pragma unroll
    for (int i = 0; i < CH; i++) {
        int idx = base + i;
        int v = 0;
        if (idx < NNODES) {
            v = g_cnt[idx];
            float d = g_deg[idx];
            g_dinv[idx] = (d > 0.f) ? rsqrtf(d) : 0.f;
        }
        loc[i] = sum;
        sum += v;
    }
    // warp inclusive scan of per-thread sums
    int inc = sum;
    #pragma unroll
    for (int off = 1; off < 32; off <<= 1) {
        int v = __shfl_up_sync(0xffffffffu, inc, off);
        if (lane >= off) inc += v;
    }
    if (lane == 31) wtot[wid] = inc;
    __syncthreads();
    if (wid == 0) {
        int v = wtot[lane];
        int wi = v;
        #pragma unroll
        for (int off = 1; off < 32; off <<= 1) {
            int u = __shfl_up_sync(0xffffffffu, wi, off);
            if (lane >= off) wi += u;
        }
        wtot[lane] = wi - v;               // exclusive warp offsets
        if (lane == 31) s_total = wi;
    }
    __syncthreads();
    int off0 = wtot[wid] + inc - sum;      // exclusive prefix for this thread
    #pragma unroll
    for (int i = 0; i < CH; i++) {
        int idx = base + i;
        if (idx < NNODES) g_rowptr[idx] = off0 + loc[i];
    }
    if (t == 0) g_rowptr[NNODES] = s_total;
}

// ---------------- launch 3: fill CSR ----------------
__global__ void k_fill(const int* __restrict__ src, const int* __restrict__ dst,
                       const float* __restrict__ w) {
    int e = blockIdx.x * blockDim.x + threadIdx.x;
    if (e < NEDGES) {
        int s = src[e], d = dst[e];
        float nm = g_dinv[s] * w[e] * g_dinv[d];
        int pos = g_rowptr[d] + atomicAdd(&g_cursor[d], 1);
        g_colsrc[pos] = s;
        g_colw[pos]   = nm;
    }
}

// ---------------- launch 4: Y = A @ X (width 300) ----------------
__global__ void k_aggY(const float* __restrict__ X) {
    __shared__ int   ss[128];
    __shared__ float sw[128];
    int n = blockIdx.x;
    int tid = threadIdx.x;
    int st = g_rowptr[n], en = g_rowptr[n + 1];
    float acc0 = 0.f, acc1 = 0.f, acc2 = 0.f;
    for (int e0 = st; e0 < en; e0 += 128) {
        int ne = min(128, en - e0);
        if (tid < ne) { ss[tid] = g_colsrc[e0 + tid]; sw[tid] = g_colw[e0 + tid]; }
        __syncthreads();
        for (int j = 0; j < ne; j++) {
            const float* xr = X + (size_t)ss[j] * FTEXT;
            float wv = sw[j];
            acc0 += wv * xr[tid];
            acc1 += wv * xr[tid + 128];
            if (tid + 256 < FTEXT) acc2 += wv * xr[tid + 256];
        }
        __syncthreads();
    }
    float* yr = g_Y + (size_t)n * FTEXT;
    yr[tid] = acc0;
    yr[tid + 128] = acc1;
    if (tid + 256 < FTEXT) yr[tid + 256] = acc2;
}

// ---------------- bf16x3 mma.sync GEMM (launches 5 and 8) ----------------
// C[M,N] = A[M,K] @ B[N,K]^T ; K-contiguous row-major; K % 4 == 0.
template<bool BIAS, bool LEAKY>
__global__ void __launch_bounds__(256, 2) mma_gemm(
    const float* __restrict__ A, int lda,
    const float* __restrict__ B, int ldb,
    float* __restrict__ C, int ldc,
    const float* __restrict__ bias,
    int M, int N, int K)
{
    extern __shared__ char smem[];
    const int STRIDE  = 40;                 // bf16 per smem row (80 B)
    const int A_BYTES = 128 * STRIDE * 2;
    const int B_BYTES = 64  * STRIDE * 2;
    const int STAGE   = 2 * A_BYTES + 2 * B_BYTES;

    int tid  = threadIdx.x;
    int wid  = tid >> 5, lane = tid & 31;
    int wm   = wid & 3;
    int wn   = wid >> 2;
    int row0 = blockIdx.y * 128;
    int col0 = blockIdx.x * 64;

    uint32_t smem_u = smem_to_u32(smem);

    float acc[2][4][4];
    #pragma unroll
    for (int mt = 0; mt < 2; mt++)
        #pragma unroll
        for (int nt = 0; nt < 4; nt++)
            #pragma unroll
            for (int q = 0; q < 4; q++) acc[mt][nt][q] = 0.f;

    float4 aR[4], bR[2];
    const int nT = (K + 31) >> 5;

    auto LDG = [&](int t) {
        int kb = t * 32;
        #pragma unroll
        for (int i = 0; i < 4; i++) {
            int idx = tid + i * 256;
            int r = idx >> 3, kk = (idx & 7) * 4;
            int row = row0 + r, kg = kb + kk;
            float4 v = make_float4(0.f, 0.f, 0.f, 0.f);
            if (row < M && kg < K) v = *(const float4*)(A + (size_t)row * lda + kg);
            aR[i] = v;
        }
        #pragma unroll
        for (int i = 0; i < 2; i++) {
            int idx = tid + i * 256;
            int c = idx >> 3, kk = (idx & 7) * 4;
            int col = col0 + c, kg = kb + kk;
            float4 v = make_float4(0.f, 0.f, 0.f, 0.f);
            if (col < N && kg < K) v = *(const float4*)(B + (size_t)col * ldb + kg);
            bR[i] = v;
        }
    };
    auto STS = [&](int s) {
        char* base = smem + s * STAGE;
        #pragma unroll
        for (int i = 0; i < 4; i++) {
            int idx = tid + i * 256;
            int r = idx >> 3, kk = (idx & 7) * 4;
            uint2 h, l;
            f4_hilo(aR[i], h, l);
            *(uint2*)(base + r * 80 + kk * 2) = h;
            *(uint2*)(base + A_BYTES + r * 80 + kk * 2) = l;
        }
        #pragma unroll
        for (int i = 0; i < 2; i++) {
            int idx = tid + i * 256;
            int c = idx >> 3, kk = (idx & 7) * 4;
            uint2 h, l;
            f4_hilo(bR[i], h, l);
            *(uint2*)(base + 2 * A_BYTES + c * 80 + kk * 2) = h;
            *(uint2*)(base + 2 * A_BYTES + B_BYTES + c * 80 + kk * 2) = l;
        }
    };
    auto COMPUTE = [&](int s) {
        uint32_t sb = smem_u + s * STAGE;
        uint32_t aH = sb + (uint32_t)((wm * 32 + (lane & 15)) * 80 + (lane >> 4) * 16);
        uint32_t aL = aH + A_BYTES;
        uint32_t bH = sb + 2 * A_BYTES +
            (uint32_t)((wn * 32 + ((lane >> 4) & 1) * 8 + (lane & 7)) * 80 + ((lane >> 3) & 1) * 16);
        uint32_t bL = bH + B_BYTES;
        #pragma unroll
        for (int ks = 0; ks < 2; ks++) {
            uint32_t ah[2][4], al[2][4], bh[2][4], bl[2][4];
            #pragma unroll
            for (int mt = 0; mt < 2; mt++) {
                ldsm_x4(ah[mt], aH + mt * 16 * 80 + ks * 32);
                ldsm_x4(al[mt], aL + mt * 16 * 80 + ks * 32);
            }
            #pragma unroll
            for (int g = 0; g < 2; g++) {
                ldsm_x4(bh[g], bH + g * 16 * 80 + ks * 32);
                ldsm_x4(bl[g], bL + g * 16 * 80 + ks * 32);
            }
            #pragma unroll
            for (int mt = 0; mt < 2; mt++)
                #pragma unroll
                for (int nt = 0; nt < 4; nt++) {
                    const uint32_t* ph = &bh[nt >> 1][(nt & 1) * 2];
                    const uint32_t* pl = &bl[nt >> 1][(nt & 1) * 2];
                    mma_bf16(acc[mt][nt], ah[mt], ph);
                    mma_bf16(acc[mt][nt], ah[mt], pl);
                    mma_bf16(acc[mt][nt], al[mt], ph);
                }
        }
    };

    LDG(0);
    STS(0);
    if (nT > 1) LDG(1);
    __syncthreads();
    for (int t = 0; t < nT; t++) {
        COMPUTE(t & 1);
        if (t + 1 < nT) STS((t + 1) & 1);
        __syncthreads();
        if (t + 2 < nT) LDG(t + 2);
    }

    int rw = row0 + wm * 32;
    int cw = col0 + wn * 32;
    #pragma unroll
    for (int mt = 0; mt < 2; mt++) {
        #pragma unroll
        for (int half = 0; half < 2; half++) {
            int row = rw + mt * 16 + (lane >> 2) + half * 8;
            if (row >= M) continue;
            #pragma unroll
            for (int nt = 0; nt < 4; nt++) {
                int col = cw + nt * 8 + (lane & 3) * 2;
                if (col >= N) continue;
                float v0 = acc[mt][nt][half * 2 + 0];
                float v1 = acc[mt][nt][half * 2 + 1];
                if (BIAS) { v0 += bias[col]; v1 += bias[col + 1]; }
                if (LEAKY) {
                    v0 = (v0 >= 0.f) ? v0 : NEG_SLOPE * v0;
                    v1 = (v1 >= 0.f) ? v1 : NEG_SLOPE * v1;
                }
                float2 o; o.x = v0; o.y = v1;
                *(float2*)(C + (size_t)row * ldc + col) = o;
            }
        }
    }
}

// ---------------- launch 6: T1 split-K SIMT fp32 ----------------
// part[s][b][n] = sum over k in [s*128, s*128+128) of img[b,k] * W2[n,k]
__global__ void __launch_bounds__(256) k_t1_splitk(
    const float* __restrict__ img, const float* __restrict__ W2)
{
    const int BK = 16;
    __shared__ float As[BK][64 + 1];
    __shared__ float Bs[BK][64 + 1];
    int tid = threadIdx.x;
    int tx = tid & 15, ty = tid >> 4;
    int col0 = blockIdx.x * 64;
    int s = blockIdx.y;
    int kbase = s * 128;

    float acc[4][4] = {};
    int r = tid >> 2, kq = (tid & 3) * 4;

    for (int t0 = 0; t0 < 128; t0 += BK) {
        float4 av = *(const float4*)(img + (size_t)r * FOUT + kbase + t0 + kq);
        As[kq + 0][r] = av.x; As[kq + 1][r] = av.y;
        As[kq + 2][r] = av.z; As[kq + 3][r] = av.w;
        float4 bv = *(const float4*)(W2 + (size_t)(col0 + r) * FOUT + kbase + t0 + kq);
        Bs[kq + 0][r] = bv.x; Bs[kq + 1][r] = bv.y;
        Bs[kq + 2][r] = bv.z; Bs[kq + 3][r] = bv.w;
        __syncthreads();
        #pragma unroll
        for (int k = 0; k < BK; k++) {
            float a[4], b[4];
            #pragma unroll
            for (int i = 0; i < 4; i++) a[i] = As[k][ty * 4 + i];
            #pragma unroll
            for (int j = 0; j < 4; j++) b[j] = Bs[k][tx * 4 + j];
            #pragma unroll
            for (int i = 0; i < 4; i++)
                #pragma unroll
                for (int j = 0; j < 4; j++)
                    acc[i][j] += a[i] * b[j];
        }
        __syncthreads();
    }
    float* cp = g_T1p + (size_t)s * (BBATCH * FHID);
    #pragma unroll
    for (int i = 0; i < 4; i++) {
        int b = ty * 4 + i;
        #pragma unroll
        for (int j = 0; j < 4; j++)
            cp[(size_t)b * FHID + col0 + tx * 4 + j] = acc[i][j];
    }
}

// ---------------- launch 7: reduce T1 partials + imgb2 ----------------
__global__ void k_t1_reduce(const float* __restrict__ img, const float* __restrict__ b2) {
    if (blockIdx.x < 256) {
        int idx = blockIdx.x * 256 + threadIdx.x;   // 0..65535
        float acc = 0.f;
        #pragma unroll
        for (int s = 0; s < NSPLIT; s++)
            acc += g_T1p[(size_t)s * (BBATCH * FHID) + idx];
        g_T1[idx] = acc;
    } else {
        // imgb2[b] = dot(img[b,:], b2); 8 warps x 8 b's each
        int wid = threadIdx.x >> 5, lane = threadIdx.x & 31;
        for (int i = 0; i < 8; i++) {
            int b = wid * 8 + i;
            float acc = 0.f;
            for (int k = lane; k < FOUT; k += 32)
                acc += img[(size_t)b * FOUT + k] * b2[k];
            #pragma unroll
            for (int off = 16; off > 0; off >>= 1)
                acc += __shfl_down_sync(0xffffffffu, acc, off);
            if (lane == 0) g_imgb2[b] = acc;
        }
    }
}

// ---------------- launch 9: output aggregation + fused transpose ----------------
// out[b, n] = imgb2[b] + sum incoming norm * T2[src, b]
__global__ void __launch_bounds__(256) k_aggOutT(float* __restrict__ out) {
    __shared__ float s[32][65];
    int n0 = blockIdx.x * 32;
    int tid = threadIdx.x;
    int slot = tid >> 6;                 // 0..3
    int b = tid & 63;
    float bias = g_imgb2[b];
    for (int rnd = 0; rnd < 8; rnd++) {
        int nl = rnd * 4 + slot;
        int n = n0 + nl;
        float acc = bias;
        int st = g_rowptr[n], en = g_rowptr[n + 1];
        for (int e = st; e < en; e++)
            acc += g_colw[e] * g_T2[(size_t)g_colsrc[e] * BBATCH + b];
        s[nl][b] = acc;
    }
    __syncthreads();
    #pragma unroll
    for (int i = 0; i < 8; i++) {
        int idx = tid + i * 256;         // 0..2047
        int bb = idx >> 5, nn = idx & 31;
        out[(size_t)bb * NNODES + n0 + nn] = s[nn][bb];
    }
}

// ---------------- launch ----------------
extern "C" void kernel_launch(void* const* d_in, const int* in_sizes, int n_in,
                              void* d_out, int out_size) {
    const float* img  = (const float*)d_in[0];
    const float* nf   = (const float*)d_in[1];
    const int*   esrc = (const int*)d_in[2];
    const int*   edst = (const int*)d_in[3];
    const float* ew   = (const float*)d_in[4];
    const float* W1   = (const float*)d_in[5];
    const float* b1   = (const float*)d_in[6];
    const float* W2   = (const float*)d_in[7];
    const float* b2   = (const float*)d_in[8];
    float* out = (float*)d_out;

    float* dY;   cudaGetSymbolAddress((void**)&dY,   g_Y);
    float* dX1;  cudaGetSymbolAddress((void**)&dX1,  g_X1);
    float* dW1t; cudaGetSymbolAddress((void**)&dW1t, g_W1t);
    float* dT1;  cudaGetSymbolAddress((void**)&dT1,  g_T1);
    float* dT2;  cudaGetSymbolAddress((void**)&dT2,  g_T2);

    const int SMEM = 61440;
    cudaFuncSetAttribute(mma_gemm<true,  true >, cudaFuncAttributeMaxDynamicSharedMemorySize, SMEM);
    cudaFuncSetAttribute(mma_gemm<false, false>, cudaFuncAttributeMaxDynamicSharedMemorySize, SMEM);

    // 0: zero scratch + transpose W1
    k_init<<<79 + 320, 256>>>(W1);
    // 1: degrees
    k_deg<<<(NEDGES + 255) / 256, 256>>>(edst, ew);
    // 2: scan + dinv
    k_scandinv<<<1, 1024>>>();
    // 3: CSR fill
    k_fill<<<(NEDGES + 255) / 256, 256>>>(esrc, edst, ew);
    // 4: layer-1 aggregation (width 300)
    k_aggY<<<NNODES, 128>>>(nf);
    // 5: X1 = leaky(Y @ W1 + b1)   <-- profiled launch
    {
        dim3 grid(FHID / 64, (NNODES + 127) / 128);
        mma_gemm<true, true><<<grid, 256, SMEM>>>(
            dY, FTEXT, dW1t, FTEXT, dX1, FHID, b1, NNODES, FHID, FTEXT);
    }
    // 6: T1 partials (split-K SIMT fp32)
    {
        dim3 grid(FHID / 64, NSPLIT);
        k_t1_splitk<<<grid, 256>>>(img, W2);
    }
    // 7: reduce T1 + imgb2
    k_t1_reduce<<<257, 256>>>(img, b2);
    // 8: T2 = X1 @ T1^T
    {
        dim3 grid(1, (NNODES + 127) / 128);
        mma_gemm<false, false><<<grid, 256, SMEM>>>(
            dX1, FHID, dT1, FHID, dT2, BBATCH, nullptr, NNODES, BBATCH, FHID);
    }
    // 9: output aggregation + fused transpose
    k_aggOutT<<<NNODES / 32, 256>>>(out);
}